// round 10
// baseline (speedup 1.0000x reference)
#include <cuda_runtime.h>
#include <cuda_fp16.h>
#include <cstdint>

#define B_   32
#define C_   768
#define HW_  1024

// -------- device scratch (allocation-free) --------
__device__ __half g_Xn[B_ * C_ * HW_];     // normalized X, fp16
__device__ __half g_Wb[2 * C_ * C_];       // interleaved fp16 weights [cb12][128][768]

// -------- GEMM tiling: M=128 (64 ch K/V-interleaved), N-stage=128, K-stage=32 --------
#define NSTG   24            // K stages per n-chunk (32 K each -> 768)
#define NCHUNK 8             // hw chunks of 128 columns
#define NGS    (NSTG * NCHUNK)

#define SMEM_A_BYTES  (128 * 768 * 2)                // 196608
#define SMEM_B_OFF    SMEM_A_BYTES
#define SLOT_BYTES    (32 * 128 * 2)                 // 8192 per stage
#define SMEM_S_OFF    (SMEM_B_OFF + 3 * SLOT_BYTES)  // 221184
#define SMEM_G_TOTAL  (SMEM_S_OFF + 1024)            // 222208

// norm kernel smem
#define SMEM_N_TOTAL  (768 * 64 * 4 + 1024 * 4)      // 200704

// -------- PTX helpers --------
__device__ __forceinline__ void cp16(uint32_t dst, const void* src) {
    asm volatile("cp.async.cg.shared.global [%0], [%1], 16;\n" :: "r"(dst), "l"(src) : "memory");
}
#define CP_COMMIT() asm volatile("cp.async.commit_group;\n" ::: "memory")
#define CP_WAIT(n)  asm volatile("cp.async.wait_group %0;\n" :: "n"(n) : "memory")

// ---------------------------------------------------------------------------
// Kernel 1: fused one-pass RMSNorm (blocks 0..511) + weight prep (512..543)
// ---------------------------------------------------------------------------
__global__ void __launch_bounds__(1024, 1)
norm_wprep_kernel(const float* __restrict__ X, const float* __restrict__ Win) {
    extern __shared__ float sm[];
    const int bid = blockIdx.x;
    const int t = threadIdx.x;

    if (bid < 512) {
        float* cache = sm;
        float* red = sm + 768 * 64;
        const int b = bid >> 4;
        const int hwb = (bid & 15) * 64;
        const int hw = t & 63;
        const int qc = t >> 6;
        const int c0 = qc * 48;

        const float* xp = X + ((size_t)b * C_ + c0) * HW_ + hwb + hw;
        float s = 0.f;
#pragma unroll 8
        for (int c = 0; c < 48; c++) {
            float v = xp[c * HW_];
            cache[(c0 + c) * 64 + hw] = v;
            s = fmaf(v, v, s);
        }
        red[t] = s;
        __syncthreads();
        float tot = 0.f;
#pragma unroll
        for (int k = 0; k < 16; k++) tot += red[k * 64 + hw];
        float inv = rsqrtf(tot * (1.0f / C_) + 1e-6f);

        __half* op = g_Xn + ((size_t)b * C_ + c0) * HW_ + hwb + hw;
#pragma unroll 8
        for (int c = 0; c < 48; c++)
            op[c * HW_] = __float2half(cache[(c0 + c) * 64 + hw] * inv);
    } else {
        // g_Wb row (cb*128 + a): g=a/16, r=a%16;
        // r<8 -> Wk[cb*64+g*8+r], else Wv[cb*64+g*8+(r-8)]
        const int base = (bid - 512) * 9216;
#pragma unroll
        for (int k = 0; k < 9; k++) {
            int i4 = base + k * 1024 + t;
            int row = i4 / 192;
            int kc = (i4 - row * 192) * 4;
            int cb = row >> 7, a = row & 127;
            int g = a >> 4, r = a & 15;
            int wrow = (r < 8) ? (cb * 64 + g * 8 + r)
                               : (C_ + cb * 64 + g * 8 + (r - 8));
            float4 v = *(const float4*)(Win + (size_t)wrow * C_ + kc);
            __half2 p0 = __floats2half2_rn(v.x, v.y);
            __half2 p1 = __floats2half2_rn(v.z, v.w);
            uint2 o;
            o.x = *(uint32_t*)&p0;
            o.y = *(uint32_t*)&p1;
            *(uint2*)(g_Wb + (size_t)row * C_ + kc) = o;
        }
    }
}

// ---------------------------------------------------------------------------
// Kernel 2: fused KV-GEMM (mma.sync, fp16 accumulate) + cosine gate + scaling.
// grid (12, 32), 256 threads = 8 warps (4 M-warps x 2 N-warps).
// B: 32K x 128N stages, 3-slot cp.async ring, loads issued 2 stages ahead.
// ---------------------------------------------------------------------------
__global__ void __launch_bounds__(256, 1)
attn_gemm_kernel(const float* __restrict__ X, float* __restrict__ out) {
    extern __shared__ char smem[];
    const uint32_t sb = (uint32_t)__cvta_generic_to_shared(smem);
    float* sS = (float*)(smem + SMEM_S_OFF);       // [64][3]
    float* sGate = sS + 192;                       // [64]

    const int tid = threadIdx.x;
    const int b = blockIdx.y;
    const int cb = blockIdx.x;

    if (tid < 192) sS[tid] = 0.f;

    // ---- A panel: XOR-swizzled ----
    const __half* wsrc = g_Wb + (size_t)cb * 128 * C_;
    for (int unit = tid; unit < 12288; unit += 256) {
        int row = unit / 96, c16 = unit - (unit / 96) * 96;
        uint32_t dst = sb + (uint32_t)(row * 1536 +
            (((c16 & 7) ^ (row & 7)) << 4) + ((c16 >> 3) << 7));
        cp16(dst, wsrc + (size_t)row * C_ + c16 * 8);
    }
    CP_COMMIT();

    const __half* XnB = g_Xn + (size_t)b * C_ * HW_;
    const int warp = tid >> 5, lane = tid & 31;
    const int wm = warp >> 1, wn = warp & 1;

    const int l_kr = tid >> 3;     // 0..31
    const int l_u  = tid & 7;      // 16B units u and u+8

#define LOAD_B(gs_)                                                            \
    {                                                                          \
        int ch_ = (gs_) / NSTG, st_ = (gs_) - ch_ * NSTG, buf_ = (gs_) % 3;    \
        const __half* src_ =                                                   \
            XnB + (size_t)(st_ * 32 + l_kr) * HW_ + ch_ * 128 + l_u * 8;       \
        uint32_t dst_ = sb + SMEM_B_OFF + buf_ * SLOT_BYTES + l_kr * 256 +     \
                        (((l_u ^ l_kr) & 7) << 4);                             \
        cp16(dst_, src_);                                                      \
        cp16(dst_ + 128, src_ + 64);                                           \
        CP_COMMIT();                                                           \
    }

    LOAD_B(0);
    LOAD_B(1);

    float skv[2] = {0.f, 0.f}, skk[2] = {0.f, 0.f}, svv[2] = {0.f, 0.f};
    uint32_t acc[2][8][2];     // packed f16x2 accumulators

#pragma unroll 1
    for (int gs = 0; gs < NGS; gs++) {
        const int st = gs % NSTG;

        if (gs < NGS - 1) { CP_WAIT(1); } else { CP_WAIT(0); }
        __syncthreads();
        if (gs + 2 < NGS) LOAD_B(gs + 2);

        if (st == 0) {
#pragma unroll
            for (int mi = 0; mi < 2; mi++)
#pragma unroll
                for (int ni = 0; ni < 8; ni++) {
                    acc[mi][ni][0] = 0u;
                    acc[mi][ni][1] = 0u;
                }
        }

        const uint32_t sBb = sb + SMEM_B_OFF + (gs % 3) * SLOT_BYTES;
#pragma unroll
        for (int kk = 0; kk < 2; kk++) {
            uint32_t af[2][4];
#pragma unroll
            for (int mi = 0; mi < 2; mi++) {
                int row = wm * 32 + mi * 16 + (lane & 15);
                int c16 = st * 4 + kk * 2 + (lane >> 4);
                uint32_t addr = sb + (uint32_t)(row * 1536 +
                    (((c16 & 7) ^ (row & 7)) << 4) + ((c16 >> 3) << 7));
                asm volatile(
                    "ldmatrix.sync.aligned.m8n8.x4.shared.b16 {%0,%1,%2,%3}, [%4];"
                    : "=r"(af[mi][0]), "=r"(af[mi][1]), "=r"(af[mi][2]), "=r"(af[mi][3])
                    : "r"(addr));
            }
            uint32_t bfr[8][2];
#pragma unroll
            for (int nj = 0; nj < 4; nj++) {
                int kr = kk * 16 + (lane & 15);
                int n16 = wn * 8 + nj * 2 + (lane >> 4);
                uint32_t addr = sBb + (uint32_t)(kr * 256 +
                    (((n16 & 7) ^ (kr & 7)) << 4) + ((n16 >> 3) << 7));
                uint32_t r0, r1, r2, r3;
                asm volatile(
                    "ldmatrix.sync.aligned.m8n8.x4.trans.shared.b16 {%0,%1,%2,%3}, [%4];"
                    : "=r"(r0), "=r"(r1), "=r"(r2), "=r"(r3)
                    : "r"(addr));
                bfr[nj * 2 + 0][0] = r0; bfr[nj * 2 + 0][1] = r1;
                bfr[nj * 2 + 1][0] = r2; bfr[nj * 2 + 1][1] = r3;
            }
#pragma unroll
            for (int mi = 0; mi < 2; mi++)
#pragma unroll
                for (int ni = 0; ni < 8; ni++) {
                    asm volatile(
                        "mma.sync.aligned.m16n8k16.row.col.f16.f16.f16.f16 "
                        "{%0,%1}, {%2,%3,%4,%5}, {%6,%7}, {%0,%1};"
                        : "+r"(acc[mi][ni][0]), "+r"(acc[mi][ni][1])
                        : "r"(af[mi][0]), "r"(af[mi][1]), "r"(af[mi][2]), "r"(af[mi][3]),
                          "r"(bfr[ni][0]), "r"(bfr[ni][1]));
                }
        }

        if (st == NSTG - 1) {
            // reg0 = {c0,c1} = K(channel) cols, reg1 = {c2,c3} = V(same ch) cols.
#pragma unroll
            for (int mi = 0; mi < 2; mi++)
#pragma unroll
                for (int ni = 0; ni < 8; ni++) {
                    __half2 kh = *(__half2*)&acc[mi][ni][0];
                    __half2 vh = *(__half2*)&acc[mi][ni][1];
                    float k0 = __low2float(kh), k1 = __high2float(kh);
                    float v0 = __low2float(vh), v1 = __high2float(vh);
                    skv[mi] += k0 * v0 + k1 * v1;
                    skk[mi] += k0 * k0 + k1 * k1;
                    svv[mi] += v0 * v0 + v1 * v1;
                }
        }
    }
#undef LOAD_B

    // quad reduce (lanes 4q..4q+3 share a channel row), per mi group
#pragma unroll
    for (int mi = 0; mi < 2; mi++) {
        skv[mi] += __shfl_down_sync(0xffffffffu, skv[mi], 1);
        skv[mi] += __shfl_down_sync(0xffffffffu, skv[mi], 2);
        skk[mi] += __shfl_down_sync(0xffffffffu, skk[mi], 1);
        skk[mi] += __shfl_down_sync(0xffffffffu, skk[mi], 2);
        svv[mi] += __shfl_down_sync(0xffffffffu, svv[mi], 1);
        svv[mi] += __shfl_down_sync(0xffffffffu, svv[mi], 2);
    }
    __syncthreads();
    if ((lane & 3) == 0) {
#pragma unroll
        for (int mi = 0; mi < 2; mi++) {
            int chl = (wm * 2 + mi) * 8 + (lane >> 2);
            atomicAdd(&sS[chl * 3 + 0], skv[mi]);
            atomicAdd(&sS[chl * 3 + 1], skk[mi]);
            atomicAdd(&sS[chl * 3 + 2], svv[mi]);
        }
    }
    __syncthreads();

    if (tid < 64) {
        float kv  = sS[tid * 3 + 0];
        float kk2 = sS[tid * 3 + 1];
        float vv2 = sS[tid * 3 + 2];
        float cosv = kv / ((sqrtf(kk2) + 1e-12f) * (sqrtf(vv2) + 1e-12f));
        sGate[tid] = 0.5f * cosv + 0.5f;
    }
    __syncthreads();

    // fused output scaling: this block's 64 channels x 1024 hw
    const float4* X4 = (const float4*)X;
    float4* O4 = (float4*)out;
    const size_t base4 = ((size_t)b * C_ + cb * 64) * (HW_ / 4);
#pragma unroll 4
    for (int i = tid; i < 64 * 256; i += 256) {
        int row = i >> 8;
        float a = sGate[row];
        float4 x = X4[base4 + i];
        float4 o;
        o.x = a * x.x; o.y = a * x.y; o.z = a * x.z; o.w = a * x.w;
        O4[base4 + i] = o;
    }
}

// ---------------------------------------------------------------------------
extern "C" void kernel_launch(void* const* d_in, const int* in_sizes, int n_in,
                              void* d_out, int out_size) {
    const float* X = (const float*)d_in[0];
    const float* W = (const float*)d_in[1];
    float* out = (float*)d_out;

    cudaFuncSetAttribute(norm_wprep_kernel,
                         cudaFuncAttributeMaxDynamicSharedMemorySize, SMEM_N_TOTAL);
    cudaFuncSetAttribute(attn_gemm_kernel,
                         cudaFuncAttributeMaxDynamicSharedMemorySize, SMEM_G_TOTAL);

    norm_wprep_kernel<<<544, 1024, SMEM_N_TOTAL>>>(X, W);
    attn_gemm_kernel<<<dim3(12, 32), 256, SMEM_G_TOTAL>>>(X, out);
}

// round 11
// speedup vs baseline: 1.4886x; 1.4886x over previous
#include <cuda_runtime.h>
#include <cuda_bf16.h>
#include <cstdint>

#define B_   32
#define C_   768
#define HW_  1024
#define NTILES (12 * 32)

// -------- device scratch (allocation-free) --------
__device__ __nv_bfloat16 g_Xn[B_ * C_ * HW_];     // normalized X, bf16
__device__ __nv_bfloat16 g_Wb[2 * C_ * C_];       // interleaved bf16 weights [cb12][128][768]
__device__ int           g_ctr;                   // persistent tile counter

// -------- GEMM tiling (round-3 shape): M=128, N-chunk=64, K-stage=64 --------
#define NSTG   12            // K stages of 64 per n-chunk
#define NCHUNK 16            // hw chunks of 64 columns
#define NGS    (NSTG * NCHUNK)

#define SMEM_A_BYTES  (128 * 768 * 2)                // 196608
#define SMEM_B_OFF    SMEM_A_BYTES
#define SLOT_BYTES    (64 * 64 * 2)                  // 8192 per stage
#define SMEM_S_OFF    (SMEM_B_OFF + 3 * SLOT_BYTES)  // 221184
#define SMEM_G_TOTAL  (SMEM_S_OFF + 1088)            // stats[192]+gate[64]+tile[1]+pad

// norm kernel smem
#define SMEM_N_TOTAL  (768 * 64 * 4 + 1024 * 4)      // 200704

// -------- PTX helpers --------
__device__ __forceinline__ void cp16(uint32_t dst, const void* src) {
    asm volatile("cp.async.cg.shared.global [%0], [%1], 16;\n" :: "r"(dst), "l"(src) : "memory");
}
#define CP_COMMIT() asm volatile("cp.async.commit_group;\n" ::: "memory")
#define CP_WAIT(n)  asm volatile("cp.async.wait_group %0;\n" :: "n"(n) : "memory")

// ---------------------------------------------------------------------------
// Kernel 1: fused one-pass RMSNorm (blocks 0..511) + weight prep (512..543)
// Also resets the persistent tile counter for the GEMM kernel.
// ---------------------------------------------------------------------------
__global__ void __launch_bounds__(1024, 1)
norm_wprep_kernel(const float* __restrict__ X, const float* __restrict__ Win) {
    extern __shared__ float sm[];
    const int bid = blockIdx.x;
    const int t = threadIdx.x;

    if (bid == 0 && t == 0) g_ctr = 0;

    if (bid < 512) {
        float* cache = sm;
        float* red = sm + 768 * 64;
        const int b = bid >> 4;
        const int hwb = (bid & 15) * 64;
        const int hw = t & 63;
        const int qc = t >> 6;
        const int c0 = qc * 48;

        const float* xp = X + ((size_t)b * C_ + c0) * HW_ + hwb + hw;
        float s = 0.f;
#pragma unroll 8
        for (int c = 0; c < 48; c++) {
            float v = xp[c * HW_];
            cache[(c0 + c) * 64 + hw] = v;
            s = fmaf(v, v, s);
        }
        red[t] = s;
        __syncthreads();
        float tot = 0.f;
#pragma unroll
        for (int k = 0; k < 16; k++) tot += red[k * 64 + hw];
        float inv = rsqrtf(tot * (1.0f / C_) + 1e-6f);

        __nv_bfloat16* op = g_Xn + ((size_t)b * C_ + c0) * HW_ + hwb + hw;
#pragma unroll 8
        for (int c = 0; c < 48; c++)
            op[c * HW_] = __float2bfloat16(cache[(c0 + c) * 64 + hw] * inv);
    } else {
        // g_Wb row (cb*128 + a): g=a/16, r=a%16;
        // r<8 -> Wk[cb*64+g*8+r], else Wv[cb*64+g*8+(r-8)]
        const int base = (bid - 512) * 9216;
#pragma unroll
        for (int k = 0; k < 9; k++) {
            int i4 = base + k * 1024 + t;
            int row = i4 / 192;
            int kc = (i4 - row * 192) * 4;
            int cb = row >> 7, a = row & 127;
            int g = a >> 4, r = a & 15;
            int wrow = (r < 8) ? (cb * 64 + g * 8 + r)
                               : (C_ + cb * 64 + g * 8 + (r - 8));
            float4 v = *(const float4*)(Win + (size_t)wrow * C_ + kc);
            __nv_bfloat162 p0 = __floats2bfloat162_rn(v.x, v.y);
            __nv_bfloat162 p1 = __floats2bfloat162_rn(v.z, v.w);
            uint2 o;
            o.x = *(uint32_t*)&p0;
            o.y = *(uint32_t*)&p1;
            *(uint2*)(g_Wb + (size_t)row * C_ + kc) = o;
        }
    }
}

// ---------------------------------------------------------------------------
// Kernel 2: PERSISTENT fused KV-GEMM (mma.sync bf16/f32) + gate + scaling.
// 152 blocks x 256 threads; tiles (cb,b) pulled from an atomic counter,
// cb-major so the 192KB A panel is reused across ~32 consecutive tiles.
// ---------------------------------------------------------------------------
__global__ void __launch_bounds__(256, 1)
attn_gemm_kernel(const float* __restrict__ X, float* __restrict__ out) {
    extern __shared__ char smem[];
    const uint32_t sb = (uint32_t)__cvta_generic_to_shared(smem);
    float* sS = (float*)(smem + SMEM_S_OFF);       // [64][3]
    float* sGate = sS + 192;                       // [64]
    int*   sTile = (int*)(sGate + 64);

    const int tid = threadIdx.x;
    const int warp = tid >> 5, lane = tid & 31;
    const int wm = warp >> 1, wn = warp & 1;
    const int l_krow = tid >> 3;            // 0..31
    const int l_n16  = tid & 7;

    int my_cb = -1;

    for (;;) {
        __syncthreads();                    // smem quiesce between tiles
        if (tid == 0) *sTile = atomicAdd(&g_ctr, 1);
        __syncthreads();
        const int t = *sTile;
        if (t >= NTILES) break;
        const int cb = t >> 5;              // cb-major ordering
        const int b  = t & 31;

        if (tid < 192) sS[tid] = 0.f;

        // ---- A panel reload only when cb changes ----
        if (cb != my_cb) {
            my_cb = cb;
            const __nv_bfloat16* wsrc = g_Wb + (size_t)cb * 128 * C_;
            for (int unit = tid; unit < 12288; unit += 256) {
                int row = unit / 96, c16 = unit - (unit / 96) * 96;
                uint32_t dst = sb + (uint32_t)(row * 1536 +
                    (((c16 & 7) ^ (row & 7)) << 4) + ((c16 >> 3) << 7));
                cp16(dst, wsrc + (size_t)row * C_ + c16 * 8);
            }
            CP_COMMIT();
        }

        const __nv_bfloat16* XnB = g_Xn + (size_t)b * C_ * HW_;

#define LOAD_B(gs_)                                                          \
    {                                                                        \
        int ch_ = (gs_) / NSTG, st_ = (gs_) - ch_ * NSTG, buf_ = (gs_) % 3;  \
        const __nv_bfloat16* src_ = XnB + (size_t)(st_ * 64) * HW_ + ch_ * 64; \
        _Pragma("unroll")                                                    \
        for (int i_ = 0; i_ < 2; i_++) {                                     \
            int kr_ = l_krow + i_ * 32;                                      \
            cp16(sb + SMEM_B_OFF + buf_ * SLOT_BYTES + kr_ * 128 +           \
                     ((l_n16 ^ (kr_ & 7)) << 4),                             \
                 src_ + (size_t)kr_ * HW_ + l_n16 * 8);                      \
        }                                                                    \
        CP_COMMIT();                                                         \
    }

        LOAD_B(0);
        LOAD_B(1);

        float skv[2] = {0.f, 0.f}, skk[2] = {0.f, 0.f}, svv[2] = {0.f, 0.f};
        float acc[2][4][4];

#pragma unroll 1
        for (int gs = 0; gs < NGS; gs++) {
            const int st = gs % NSTG;
            const int buf = gs % 3;

            if (gs < NGS - 1) { CP_WAIT(1); } else { CP_WAIT(0); }
            __syncthreads();
            if (gs + 2 < NGS) LOAD_B(gs + 2);

            if (st == 0) {
#pragma unroll
                for (int mi = 0; mi < 2; mi++)
#pragma unroll
                    for (int ni = 0; ni < 4; ni++)
#pragma unroll
                        for (int q = 0; q < 4; q++) acc[mi][ni][q] = 0.f;
            }

            const uint32_t sBb = sb + SMEM_B_OFF + buf * SLOT_BYTES;
#pragma unroll
            for (int kk = 0; kk < 4; kk++) {
                const int c16b = st * 8 + kk * 2;
                uint32_t af[2][4];
#pragma unroll
                for (int mi = 0; mi < 2; mi++) {
                    int row = wm * 32 + mi * 16 + (lane & 15);
                    int c16 = c16b + (lane >> 4);
                    uint32_t addr = sb + (uint32_t)(row * 1536 +
                        (((c16 & 7) ^ (row & 7)) << 4) + ((c16 >> 3) << 7));
                    asm volatile(
                        "ldmatrix.sync.aligned.m8n8.x4.shared.b16 {%0,%1,%2,%3}, [%4];"
                        : "=r"(af[mi][0]), "=r"(af[mi][1]), "=r"(af[mi][2]), "=r"(af[mi][3])
                        : "r"(addr));
                }
                uint32_t bfr[4][2];
#pragma unroll
                for (int nj = 0; nj < 2; nj++) {
                    int krow = kk * 16 + (lane & 15);
                    int n16 = wn * 4 + nj * 2 + (lane >> 4);
                    uint32_t addr = sBb + (uint32_t)(krow * 128 + ((n16 ^ (krow & 7)) << 4));
                    uint32_t r0, r1, r2, r3;
                    asm volatile(
                        "ldmatrix.sync.aligned.m8n8.x4.trans.shared.b16 {%0,%1,%2,%3}, [%4];"
                        : "=r"(r0), "=r"(r1), "=r"(r2), "=r"(r3)
                        : "r"(addr));
                    bfr[nj * 2 + 0][0] = r0; bfr[nj * 2 + 0][1] = r1;
                    bfr[nj * 2 + 1][0] = r2; bfr[nj * 2 + 1][1] = r3;
                }
#pragma unroll
                for (int mi = 0; mi < 2; mi++)
#pragma unroll
                    for (int ni = 0; ni < 4; ni++) {
                        asm volatile(
                            "mma.sync.aligned.m16n8k16.row.col.f32.bf16.bf16.f32 "
                            "{%0,%1,%2,%3}, {%4,%5,%6,%7}, {%8,%9}, {%0,%1,%2,%3};"
                            : "+f"(acc[mi][ni][0]), "+f"(acc[mi][ni][1]),
                              "+f"(acc[mi][ni][2]), "+f"(acc[mi][ni][3])
                            : "r"(af[mi][0]), "r"(af[mi][1]), "r"(af[mi][2]), "r"(af[mi][3]),
                              "r"(bfr[ni][0]), "r"(bfr[ni][1]));
                    }
            }

            if (st == NSTG - 1) {
                // d0,d1 = K(ch), d2,d3 = V(same ch), same columns.
#pragma unroll
                for (int mi = 0; mi < 2; mi++)
#pragma unroll
                    for (int ni = 0; ni < 4; ni++) {
                        float k0 = acc[mi][ni][0], k1 = acc[mi][ni][1];
                        float v0 = acc[mi][ni][2], v1 = acc[mi][ni][3];
                        skv[mi] += k0 * v0 + k1 * v1;
                        skk[mi] += k0 * k0 + k1 * k1;
                        svv[mi] += v0 * v0 + v1 * v1;
                    }
            }
        }
#undef LOAD_B

        // quad reduce (lanes 4q..4q+3 share a channel row), per mi group
#pragma unroll
        for (int mi = 0; mi < 2; mi++) {
            skv[mi] += __shfl_down_sync(0xffffffffu, skv[mi], 1);
            skv[mi] += __shfl_down_sync(0xffffffffu, skv[mi], 2);
            skk[mi] += __shfl_down_sync(0xffffffffu, skk[mi], 1);
            skk[mi] += __shfl_down_sync(0xffffffffu, skk[mi], 2);
            svv[mi] += __shfl_down_sync(0xffffffffu, svv[mi], 1);
            svv[mi] += __shfl_down_sync(0xffffffffu, svv[mi], 2);
        }
        __syncthreads();
        if ((lane & 3) == 0) {
#pragma unroll
            for (int mi = 0; mi < 2; mi++) {
                int chl = (wm * 2 + mi) * 8 + (lane >> 2);
                atomicAdd(&sS[chl * 3 + 0], skv[mi]);
                atomicAdd(&sS[chl * 3 + 1], skk[mi]);
                atomicAdd(&sS[chl * 3 + 2], svv[mi]);
            }
        }
        __syncthreads();

        if (tid < 64) {
            float kv  = sS[tid * 3 + 0];
            float kk2 = sS[tid * 3 + 1];
            float vv2 = sS[tid * 3 + 2];
            float cosv = kv / ((sqrtf(kk2) + 1e-12f) * (sqrtf(vv2) + 1e-12f));
            sGate[tid] = 0.5f * cosv + 0.5f;
        }
        __syncthreads();

        // fused output scaling: this tile's 64 channels x 1024 hw
        const float4* X4 = (const float4*)X;
        float4* O4 = (float4*)out;
        const size_t base4 = ((size_t)b * C_ + cb * 64) * (HW_ / 4);
#pragma unroll 4
        for (int i = tid; i < 64 * 256; i += 256) {
            int row = i >> 8;
            float a = sGate[row];
            float4 x = X4[base4 + i];
            float4 o;
            o.x = a * x.x; o.y = a * x.y; o.z = a * x.z; o.w = a * x.w;
            O4[base4 + i] = o;
        }
    }
}

// ---------------------------------------------------------------------------
extern "C" void kernel_launch(void* const* d_in, const int* in_sizes, int n_in,
                              void* d_out, int out_size) {
    const float* X = (const float*)d_in[0];
    const float* W = (const float*)d_in[1];
    float* out = (float*)d_out;

    cudaFuncSetAttribute(norm_wprep_kernel,
                         cudaFuncAttributeMaxDynamicSharedMemorySize, SMEM_N_TOTAL);
    cudaFuncSetAttribute(attn_gemm_kernel,
                         cudaFuncAttributeMaxDynamicSharedMemorySize, SMEM_G_TOTAL);

    norm_wprep_kernel<<<544, 1024, SMEM_N_TOTAL>>>(X, W);
    attn_gemm_kernel<<<152, 256, SMEM_G_TOTAL>>>(X, out);
}

// round 12
// speedup vs baseline: 1.5362x; 1.0320x over previous
#include <cuda_runtime.h>
#include <cuda_bf16.h>
#include <cstdint>

#define B_   32
#define C_   768
#define HW_  1024
#define NTILES (12 * 32)

// -------- device scratch (allocation-free) --------
__device__ __nv_bfloat16 g_Xn[B_ * C_ * HW_];     // normalized X, bf16
__device__ __nv_bfloat16 g_Wb[2 * C_ * C_];       // interleaved bf16 weights [cb12][128][768]
__device__ int           g_ctr;                   // persistent tile counter

// -------- GEMM tiling: M=128, N-chunk=64, K-stage=64 --------
#define NSTG   12
#define NCHUNK 16
#define NGS    (NSTG * NCHUNK)

#define SMEM_A_BYTES  (128 * 768 * 2)                // 196608
#define SMEM_B_OFF    SMEM_A_BYTES
#define SLOT_BYTES    (64 * 64 * 2)                  // 8192 per stage
#define SMEM_S_OFF    (SMEM_B_OFF + 3 * SLOT_BYTES)  // 221184
#define SMEM_G_TOTAL  (SMEM_S_OFF + 1088)

// norm kernel smem
#define SMEM_N_TOTAL  (768 * 64 * 4 + 1024 * 4)      // 200704

// -------- PTX helpers --------
__device__ __forceinline__ void cp16(uint32_t dst, const void* src) {
    asm volatile("cp.async.cg.shared.global [%0], [%1], 16;\n" :: "r"(dst), "l"(src) : "memory");
}
#define CP_COMMIT() asm volatile("cp.async.commit_group;\n" ::: "memory")
#define CP_WAIT(n)  asm volatile("cp.async.wait_group %0;\n" :: "n"(n) : "memory")

// ---------------------------------------------------------------------------
// Kernel 1: fused one-pass RMSNorm (blocks 0..511) + weight prep (512..543)
// Also resets the persistent tile counter for the GEMM kernel.
// ---------------------------------------------------------------------------
__global__ void __launch_bounds__(1024, 1)
norm_wprep_kernel(const float* __restrict__ X, const float* __restrict__ Win) {
    extern __shared__ float sm[];
    const int bid = blockIdx.x;
    const int t = threadIdx.x;

    if (bid == 0 && t == 0) g_ctr = 0;

    if (bid < 512) {
        float* cache = sm;
        float* red = sm + 768 * 64;
        const int b = bid >> 4;
        const int hwb = (bid & 15) * 64;
        const int hw = t & 63;
        const int qc = t >> 6;
        const int c0 = qc * 48;

        const float* xp = X + ((size_t)b * C_ + c0) * HW_ + hwb + hw;
        float s = 0.f;
#pragma unroll 8
        for (int c = 0; c < 48; c++) {
            float v = xp[c * HW_];
            cache[(c0 + c) * 64 + hw] = v;
            s = fmaf(v, v, s);
        }
        red[t] = s;
        __syncthreads();
        float tot = 0.f;
#pragma unroll
        for (int k = 0; k < 16; k++) tot += red[k * 64 + hw];
        float inv = rsqrtf(tot * (1.0f / C_) + 1e-6f);

        __nv_bfloat16* op = g_Xn + ((size_t)b * C_ + c0) * HW_ + hwb + hw;
#pragma unroll 8
        for (int c = 0; c < 48; c++)
            op[c * HW_] = __float2bfloat16(cache[(c0 + c) * 64 + hw] * inv);
    } else {
        // g_Wb row (cb*128 + a): g=a/16, r=a%16;
        // r<8 -> Wk[cb*64+g*8+r], else Wv[cb*64+g*8+(r-8)]
        const int base = (bid - 512) * 9216;
#pragma unroll
        for (int k = 0; k < 9; k++) {
            int i4 = base + k * 1024 + t;
            int row = i4 / 192;
            int kc = (i4 - row * 192) * 4;
            int cb = row >> 7, a = row & 127;
            int g = a >> 4, r = a & 15;
            int wrow = (r < 8) ? (cb * 64 + g * 8 + r)
                               : (C_ + cb * 64 + g * 8 + (r - 8));
            float4 v = *(const float4*)(Win + (size_t)wrow * C_ + kc);
            __nv_bfloat162 p0 = __floats2bfloat162_rn(v.x, v.y);
            __nv_bfloat162 p1 = __floats2bfloat162_rn(v.z, v.w);
            uint2 o;
            o.x = *(uint32_t*)&p0;
            o.y = *(uint32_t*)&p1;
            *(uint2*)(g_Wb + (size_t)row * C_ + kc) = o;
        }
    }
}

// ---------------------------------------------------------------------------
// Kernel 2: PERSISTENT fused KV-GEMM + gate + scaling, with software-pipelined
// fragment loads (double-buffered LDSM) inside each K-stage.
// 152 blocks x 256 threads; cb-major tile order for A-panel reuse.
// ---------------------------------------------------------------------------
__global__ void __launch_bounds__(256, 1)
attn_gemm_kernel(const float* __restrict__ X, float* __restrict__ out) {
    extern __shared__ char smem[];
    const uint32_t sb = (uint32_t)__cvta_generic_to_shared(smem);
    float* sS = (float*)(smem + SMEM_S_OFF);       // [64][3]
    float* sGate = sS + 192;                       // [64]
    int*   sTile = (int*)(sGate + 64);

    const int tid = threadIdx.x;
    const int warp = tid >> 5, lane = tid & 31;
    const int wm = warp >> 1, wn = warp & 1;
    const int l_krow = tid >> 3;            // 0..31
    const int l_n16  = tid & 7;

    // Per-thread invariant pieces of LDSM addresses
    const int a_row_base = wm * 32 + (lane & 15);      // + mi*16
    const int a_c16_lo   = (lane >> 4);                // + kk*2 + st*8
    const int b_kr_lane  = (lane & 15);                // + kk*16
    const int b_n16_base = wn * 4 + (lane >> 4);       // + nj*2

    int my_cb = -1;

    for (;;) {
        __syncthreads();
        if (tid == 0) *sTile = atomicAdd(&g_ctr, 1);
        __syncthreads();
        const int t = *sTile;
        if (t >= NTILES) break;
        const int cb = t >> 5;
        const int b  = t & 31;

        if (tid < 192) sS[tid] = 0.f;

        // ---- A panel reload only when cb changes ----
        if (cb != my_cb) {
            my_cb = cb;
            const __nv_bfloat16* wsrc = g_Wb + (size_t)cb * 128 * C_;
            for (int unit = tid; unit < 12288; unit += 256) {
                int row = unit / 96, c16 = unit - (unit / 96) * 96;
                uint32_t dst = sb + (uint32_t)(row * 1536 +
                    (((c16 & 7) ^ (row & 7)) << 4) + ((c16 >> 3) << 7));
                cp16(dst, wsrc + (size_t)row * C_ + c16 * 8);
            }
            CP_COMMIT();
        }

        const __nv_bfloat16* XnB = g_Xn + (size_t)b * C_ * HW_;

#define LOAD_B(gs_)                                                          \
    {                                                                        \
        int ch_ = (gs_) / NSTG, st_ = (gs_) - ch_ * NSTG, buf_ = (gs_) % 3;  \
        const __nv_bfloat16* src_ = XnB + (size_t)(st_ * 64) * HW_ + ch_ * 64; \
        _Pragma("unroll")                                                    \
        for (int i_ = 0; i_ < 2; i_++) {                                     \
            int kr_ = l_krow + i_ * 32;                                      \
            cp16(sb + SMEM_B_OFF + buf_ * SLOT_BYTES + kr_ * 128 +           \
                     ((l_n16 ^ (kr_ & 7)) << 4),                             \
                 src_ + (size_t)kr_ * HW_ + l_n16 * 8);                      \
        }                                                                    \
        CP_COMMIT();                                                         \
    }

// Load all fragments for one kk into register buffers af_/bf_
#define LD_FRAGS(kk_, st_, sBb_, af_, bf_)                                   \
    {                                                                        \
        _Pragma("unroll")                                                    \
        for (int mi = 0; mi < 2; mi++) {                                     \
            int row = a_row_base + mi * 16;                                  \
            int c16 = (st_) * 8 + (kk_) * 2 + a_c16_lo;                      \
            uint32_t addr = sb + (uint32_t)(row * 1536 +                     \
                (((c16 & 7) ^ (row & 7)) << 4) + ((c16 >> 3) << 7));         \
            asm volatile(                                                    \
                "ldmatrix.sync.aligned.m8n8.x4.shared.b16 {%0,%1,%2,%3}, [%4];" \
                : "=r"((af_)[mi][0]), "=r"((af_)[mi][1]),                    \
                  "=r"((af_)[mi][2]), "=r"((af_)[mi][3])                     \
                : "r"(addr));                                                \
        }                                                                    \
        _Pragma("unroll")                                                    \
        for (int nj = 0; nj < 2; nj++) {                                     \
            int krow = (kk_) * 16 + b_kr_lane;                               \
            int n16 = b_n16_base + nj * 2;                                   \
            uint32_t addr = (sBb_) + (uint32_t)(krow * 128 +                 \
                ((n16 ^ (krow & 7)) << 4));                                  \
            uint32_t r0, r1, r2, r3;                                         \
            asm volatile(                                                    \
                "ldmatrix.sync.aligned.m8n8.x4.trans.shared.b16 {%0,%1,%2,%3}, [%4];" \
                : "=r"(r0), "=r"(r1), "=r"(r2), "=r"(r3)                     \
                : "r"(addr));                                                \
            (bf_)[nj * 2 + 0][0] = r0; (bf_)[nj * 2 + 0][1] = r1;            \
            (bf_)[nj * 2 + 1][0] = r2; (bf_)[nj * 2 + 1][1] = r3;            \
        }                                                                    \
    }

#define MMA8(af_, bf_)                                                       \
    {                                                                        \
        _Pragma("unroll")                                                    \
        for (int mi = 0; mi < 2; mi++)                                       \
            _Pragma("unroll")                                                \
            for (int ni = 0; ni < 4; ni++) {                                 \
                asm volatile(                                                \
                    "mma.sync.aligned.m16n8k16.row.col.f32.bf16.bf16.f32 "   \
                    "{%0,%1,%2,%3}, {%4,%5,%6,%7}, {%8,%9}, {%0,%1,%2,%3};"  \
                    : "+f"(acc[mi][ni][0]), "+f"(acc[mi][ni][1]),            \
                      "+f"(acc[mi][ni][2]), "+f"(acc[mi][ni][3])             \
                    : "r"((af_)[mi][0]), "r"((af_)[mi][1]),                  \
                      "r"((af_)[mi][2]), "r"((af_)[mi][3]),                  \
                      "r"((bf_)[ni][0]), "r"((bf_)[ni][1]));                 \
            }                                                                \
    }

        LOAD_B(0);
        LOAD_B(1);

        float skv[2] = {0.f, 0.f}, skk[2] = {0.f, 0.f}, svv[2] = {0.f, 0.f};
        float acc[2][4][4];
        uint32_t afA[2][4], afB[2][4];       // double-buffered A frags
        uint32_t bfA[4][2], bfB[4][2];       // double-buffered B frags

#pragma unroll 1
        for (int gs = 0; gs < NGS; gs++) {
            const int st = gs % NSTG;
            const int buf = gs % 3;

            if (gs < NGS - 1) { CP_WAIT(1); } else { CP_WAIT(0); }
            __syncthreads();
            if (gs + 2 < NGS) LOAD_B(gs + 2);

            if (st == 0) {
#pragma unroll
                for (int mi = 0; mi < 2; mi++)
#pragma unroll
                    for (int ni = 0; ni < 4; ni++)
#pragma unroll
                        for (int q = 0; q < 4; q++) acc[mi][ni][q] = 0.f;
            }

            const uint32_t sBb = sb + SMEM_B_OFF + buf * SLOT_BYTES;

            // Software-pipelined: frag loads for kk+1 issued before MMAs of kk.
            LD_FRAGS(0, st, sBb, afA, bfA);
            LD_FRAGS(1, st, sBb, afB, bfB);
            MMA8(afA, bfA);
            LD_FRAGS(2, st, sBb, afA, bfA);
            MMA8(afB, bfB);
            LD_FRAGS(3, st, sBb, afB, bfB);
            MMA8(afA, bfA);
            MMA8(afB, bfB);

            if (st == NSTG - 1) {
                // d0,d1 = K(ch), d2,d3 = V(same ch), same columns.
#pragma unroll
                for (int mi = 0; mi < 2; mi++)
#pragma unroll
                    for (int ni = 0; ni < 4; ni++) {
                        float k0 = acc[mi][ni][0], k1 = acc[mi][ni][1];
                        float v0 = acc[mi][ni][2], v1 = acc[mi][ni][3];
                        skv[mi] += k0 * v0 + k1 * v1;
                        skk[mi] += k0 * k0 + k1 * k1;
                        svv[mi] += v0 * v0 + v1 * v1;
                    }
            }
        }
#undef LOAD_B
#undef LD_FRAGS
#undef MMA8

        // quad reduce (lanes 4q..4q+3 share a channel row), per mi group
#pragma unroll
        for (int mi = 0; mi < 2; mi++) {
            skv[mi] += __shfl_down_sync(0xffffffffu, skv[mi], 1);
            skv[mi] += __shfl_down_sync(0xffffffffu, skv[mi], 2);
            skk[mi] += __shfl_down_sync(0xffffffffu, skk[mi], 1);
            skk[mi] += __shfl_down_sync(0xffffffffu, skk[mi], 2);
            svv[mi] += __shfl_down_sync(0xffffffffu, svv[mi], 1);
            svv[mi] += __shfl_down_sync(0xffffffffu, svv[mi], 2);
        }
        __syncthreads();
        if ((lane & 3) == 0) {
#pragma unroll
            for (int mi = 0; mi < 2; mi++) {
                int chl = (wm * 2 + mi) * 8 + (lane >> 2);
                atomicAdd(&sS[chl * 3 + 0], skv[mi]);
                atomicAdd(&sS[chl * 3 + 1], skk[mi]);
                atomicAdd(&sS[chl * 3 + 2], svv[mi]);
            }
        }
        __syncthreads();

        if (tid < 64) {
            float kv  = sS[tid * 3 + 0];
            float kk2 = sS[tid * 3 + 1];
            float vv2 = sS[tid * 3 + 2];
            float cosv = kv / ((sqrtf(kk2) + 1e-12f) * (sqrtf(vv2) + 1e-12f));
            sGate[tid] = 0.5f * cosv + 0.5f;
        }
        __syncthreads();

        // fused output scaling: this tile's 64 channels x 1024 hw
        const float4* X4 = (const float4*)X;
        float4* O4 = (float4*)out;
        const size_t base4 = ((size_t)b * C_ + cb * 64) * (HW_ / 4);
#pragma unroll 4
        for (int i = tid; i < 64 * 256; i += 256) {
            int row = i >> 8;
            float a = sGate[row];
            float4 x = X4[base4 + i];
            float4 o;
            o.x = a * x.x; o.y = a * x.y; o.z = a * x.z; o.w = a * x.w;
            O4[base4 + i] = o;
        }
    }
}

// ---------------------------------------------------------------------------
extern "C" void kernel_launch(void* const* d_in, const int* in_sizes, int n_in,
                              void* d_out, int out_size) {
    const float* X = (const float*)d_in[0];
    const float* W = (const float*)d_in[1];
    float* out = (float*)d_out;

    cudaFuncSetAttribute(norm_wprep_kernel,
                         cudaFuncAttributeMaxDynamicSharedMemorySize, SMEM_N_TOTAL);
    cudaFuncSetAttribute(attn_gemm_kernel,
                         cudaFuncAttributeMaxDynamicSharedMemorySize, SMEM_G_TOTAL);

    norm_wprep_kernel<<<544, 1024, SMEM_N_TOTAL>>>(X, W);
    attn_gemm_kernel<<<152, 256, SMEM_G_TOTAL>>>(X, out);
}

// round 13
// speedup vs baseline: 1.7986x; 1.1708x over previous
#include <cuda_runtime.h>
#include <cuda_bf16.h>
#include <cstdint>

#define B_   32
#define C_   768
#define HW_  1024
#define NTILES (12 * 32)

// -------- device scratch (allocation-free) --------
__device__ __nv_bfloat16 g_Xn[B_ * C_ * HW_];     // normalized X, bf16
__device__ __nv_bfloat16 g_Wb[2 * C_ * C_];       // interleaved bf16 weights [cb12][128][768]
__device__ int           g_ctr;                   // persistent tile counter

// -------- GEMM tiling: M=128, N-chunk=64, K-stage=128 --------
#define NSTG   6             // K stages of 128 per n-chunk
#define NCHUNK 16
#define NGS    (NSTG * NCHUNK)   // 96

#define SMEM_A_BYTES  (128 * 768 * 2)                // 196608
#define SMEM_B_OFF    SMEM_A_BYTES
#define SLOT_BYTES    (128 * 64 * 2)                 // 16384 per stage
#define SMEM_S_OFF    (SMEM_B_OFF + 2 * SLOT_BYTES)  // 229376
#define SMEM_G_TOTAL  (SMEM_S_OFF + 1088)            // 230464 <= 232448

// norm kernel smem: bf16 cache + fp32 reduce
#define SMEM_N_TOTAL  (768 * 64 * 2 + 1024 * 4)      // 102400 -> 2 blocks/SM

// -------- PTX helpers --------
__device__ __forceinline__ void cp16(uint32_t dst, const void* src) {
    asm volatile("cp.async.cg.shared.global [%0], [%1], 16;\n" :: "r"(dst), "l"(src) : "memory");
}
#define CP_COMMIT() asm volatile("cp.async.commit_group;\n" ::: "memory")
#define CP_WAIT(n)  asm volatile("cp.async.wait_group %0;\n" :: "n"(n) : "memory")

// ---------------------------------------------------------------------------
// Kernel 1: fused one-pass RMSNorm (blocks 0..511, bf16 cache, occ 2)
//           + weight prep (blocks 512..543). Resets tile counter.
// ---------------------------------------------------------------------------
__global__ void __launch_bounds__(1024, 2)
norm_wprep_kernel(const float* __restrict__ X, const float* __restrict__ Win) {
    extern __shared__ char smn[];
    const int bid = blockIdx.x;
    const int t = threadIdx.x;

    if (bid == 0 && t == 0) g_ctr = 0;

    if (bid < 512) {
        __nv_bfloat16* cache = (__nv_bfloat16*)smn;          // [768*64]
        float* red = (float*)(smn + 768 * 64 * 2);           // [1024]
        const int b = bid >> 4;
        const int hwb = (bid & 15) * 64;
        const int hw = t & 63;
        const int qc = t >> 6;
        const int c0 = qc * 48;

        const float* xp = X + ((size_t)b * C_ + c0) * HW_ + hwb + hw;
        float s = 0.f;
#pragma unroll 8
        for (int c = 0; c < 48; c++) {
            float v = xp[c * HW_];
            cache[(c0 + c) * 64 + hw] = __float2bfloat16(v);
            s = fmaf(v, v, s);
        }
        red[t] = s;
        __syncthreads();
        float tot = 0.f;
#pragma unroll
        for (int k = 0; k < 16; k++) tot += red[k * 64 + hw];
        float inv = rsqrtf(tot * (1.0f / C_) + 1e-6f);

        __nv_bfloat16* op = g_Xn + ((size_t)b * C_ + c0) * HW_ + hwb + hw;
#pragma unroll 8
        for (int c = 0; c < 48; c++)
            op[c * HW_] = __float2bfloat16(
                __bfloat162float(cache[(c0 + c) * 64 + hw]) * inv);
    } else {
        // g_Wb row (cb*128 + a): g=a/16, r=a%16;
        // r<8 -> Wk[cb*64+g*8+r], else Wv[cb*64+g*8+(r-8)]
        const int base = (bid - 512) * 9216;
#pragma unroll
        for (int k = 0; k < 9; k++) {
            int i4 = base + k * 1024 + t;
            int row = i4 / 192;
            int kc = (i4 - row * 192) * 4;
            int cb = row >> 7, a = row & 127;
            int g = a >> 4, r = a & 15;
            int wrow = (r < 8) ? (cb * 64 + g * 8 + r)
                               : (C_ + cb * 64 + g * 8 + (r - 8));
            float4 v = *(const float4*)(Win + (size_t)wrow * C_ + kc);
            __nv_bfloat162 p0 = __floats2bfloat162_rn(v.x, v.y);
            __nv_bfloat162 p1 = __floats2bfloat162_rn(v.z, v.w);
            uint2 o;
            o.x = *(uint32_t*)&p0;
            o.y = *(uint32_t*)&p1;
            *(uint2*)(g_Wb + (size_t)row * C_ + kc) = o;
        }
    }
}

// ---------------------------------------------------------------------------
// Kernel 2: PERSISTENT fused KV-GEMM + gate + scaling.
// K-stage=128 (6 stages/chunk, 96 total), 2-slot double buffer,
// software-pipelined LDSM, cb-major tile order for A-panel reuse.
// ---------------------------------------------------------------------------
__global__ void __launch_bounds__(256, 1)
attn_gemm_kernel(const float* __restrict__ X, float* __restrict__ out) {
    extern __shared__ char smem[];
    const uint32_t sb = (uint32_t)__cvta_generic_to_shared(smem);
    float* sS = (float*)(smem + SMEM_S_OFF);       // [64][3]
    float* sGate = sS + 192;                       // [64]
    int*   sTile = (int*)(sGate + 64);

    const int tid = threadIdx.x;
    const int warp = tid >> 5, lane = tid & 31;
    const int wm = warp >> 1, wn = warp & 1;
    const int l_krow = tid >> 3;            // 0..31
    const int l_n16  = tid & 7;

    const int a_row_base = wm * 32 + (lane & 15);
    const int a_c16_lo   = (lane >> 4);
    const int b_kr_lane  = (lane & 15);
    const int b_n16_base = wn * 4 + (lane >> 4);

    int my_cb = -1;

    for (;;) {
        __syncthreads();
        if (tid == 0) *sTile = atomicAdd(&g_ctr, 1);
        __syncthreads();
        const int t = *sTile;
        if (t >= NTILES) break;
        const int cb = t >> 5;
        const int b  = t & 31;

        if (tid < 192) sS[tid] = 0.f;

        // ---- A panel reload only when cb changes ----
        if (cb != my_cb) {
            my_cb = cb;
            const __nv_bfloat16* wsrc = g_Wb + (size_t)cb * 128 * C_;
            for (int unit = tid; unit < 12288; unit += 256) {
                int row = unit / 96, c16 = unit - (unit / 96) * 96;
                uint32_t dst = sb + (uint32_t)(row * 1536 +
                    (((c16 & 7) ^ (row & 7)) << 4) + ((c16 >> 3) << 7));
                cp16(dst, wsrc + (size_t)row * C_ + c16 * 8);
            }
            CP_COMMIT();
        }

        const __nv_bfloat16* XnB = g_Xn + (size_t)b * C_ * HW_;

// 16KB stage: 128 K-rows x 64 N-cols; 256 threads x 4 cp16
#define LOAD_B(gs_)                                                          \
    {                                                                        \
        int ch_ = (gs_) / NSTG, st_ = (gs_) - ch_ * NSTG, buf_ = (gs_) & 1;  \
        const __nv_bfloat16* src_ =                                          \
            XnB + (size_t)(st_ * 128) * HW_ + ch_ * 64;                      \
        _Pragma("unroll")                                                    \
        for (int i_ = 0; i_ < 4; i_++) {                                     \
            int kr_ = l_krow + i_ * 32;                                      \
            cp16(sb + SMEM_B_OFF + buf_ * SLOT_BYTES + kr_ * 128 +           \
                     ((l_n16 ^ (kr_ & 7)) << 4),                             \
                 src_ + (size_t)kr_ * HW_ + l_n16 * 8);                      \
        }                                                                    \
        CP_COMMIT();                                                         \
    }

#define LD_FRAGS(kk_, st_, sBb_, af_, bf_)                                   \
    {                                                                        \
        _Pragma("unroll")                                                    \
        for (int mi = 0; mi < 2; mi++) {                                     \
            int row = a_row_base + mi * 16;                                  \
            int c16 = (st_) * 16 + (kk_) * 2 + a_c16_lo;                     \
            uint32_t addr = sb + (uint32_t)(row * 1536 +                     \
                (((c16 & 7) ^ (row & 7)) << 4) + ((c16 >> 3) << 7));         \
            asm volatile(                                                    \
                "ldmatrix.sync.aligned.m8n8.x4.shared.b16 {%0,%1,%2,%3}, [%4];" \
                : "=r"((af_)[mi][0]), "=r"((af_)[mi][1]),                    \
                  "=r"((af_)[mi][2]), "=r"((af_)[mi][3])                     \
                : "r"(addr));                                                \
        }                                                                    \
        _Pragma("unroll")                                                    \
        for (int nj = 0; nj < 2; nj++) {                                     \
            int krow = (kk_) * 16 + b_kr_lane;                               \
            int n16 = b_n16_base + nj * 2;                                   \
            uint32_t addr = (sBb_) + (uint32_t)(krow * 128 +                 \
                ((n16 ^ (krow & 7)) << 4));                                  \
            uint32_t r0, r1, r2, r3;                                         \
            asm volatile(                                                    \
                "ldmatrix.sync.aligned.m8n8.x4.trans.shared.b16 {%0,%1,%2,%3}, [%4];" \
                : "=r"(r0), "=r"(r1), "=r"(r2), "=r"(r3)                     \
                : "r"(addr));                                                \
            (bf_)[nj * 2 + 0][0] = r0; (bf_)[nj * 2 + 0][1] = r1;            \
            (bf_)[nj * 2 + 1][0] = r2; (bf_)[nj * 2 + 1][1] = r3;            \
        }                                                                    \
    }

#define MMA8(af_, bf_)                                                       \
    {                                                                        \
        _Pragma("unroll")                                                    \
        for (int mi = 0; mi < 2; mi++)                                       \
            _Pragma("unroll")                                                \
            for (int ni = 0; ni < 4; ni++) {                                 \
                asm volatile(                                                \
                    "mma.sync.aligned.m16n8k16.row.col.f32.bf16.bf16.f32 "   \
                    "{%0,%1,%2,%3}, {%4,%5,%6,%7}, {%8,%9}, {%0,%1,%2,%3};"  \
                    : "+f"(acc[mi][ni][0]), "+f"(acc[mi][ni][1]),            \
                      "+f"(acc[mi][ni][2]), "+f"(acc[mi][ni][3])             \
                    : "r"((af_)[mi][0]), "r"((af_)[mi][1]),                  \
                      "r"((af_)[mi][2]), "r"((af_)[mi][3]),                  \
                      "r"((bf_)[ni][0]), "r"((bf_)[ni][1]));                 \
            }                                                                \
    }

        LOAD_B(0);

        float skv[2] = {0.f, 0.f}, skk[2] = {0.f, 0.f}, svv[2] = {0.f, 0.f};
        float acc[2][4][4];
        uint32_t afA[2][4], afB[2][4];
        uint32_t bfA[4][2], bfB[4][2];

#pragma unroll 1
        for (int gs = 0; gs < NGS; gs++) {
            const int st = gs % NSTG;

            CP_WAIT(0);                    // only LOAD_B(gs) outstanding
            __syncthreads();               // all reads of other slot done
            if (gs + 1 < NGS) LOAD_B(gs + 1);

            if (st == 0) {
#pragma unroll
                for (int mi = 0; mi < 2; mi++)
#pragma unroll
                    for (int ni = 0; ni < 4; ni++)
#pragma unroll
                        for (int q = 0; q < 4; q++) acc[mi][ni][q] = 0.f;
            }

            const uint32_t sBb = sb + SMEM_B_OFF + (gs & 1) * SLOT_BYTES;

            // 8 kk steps, rolling double-buffered fragments
            LD_FRAGS(0, st, sBb, afA, bfA);
            LD_FRAGS(1, st, sBb, afB, bfB);
            MMA8(afA, bfA);
            LD_FRAGS(2, st, sBb, afA, bfA);
            MMA8(afB, bfB);
            LD_FRAGS(3, st, sBb, afB, bfB);
            MMA8(afA, bfA);
            LD_FRAGS(4, st, sBb, afA, bfA);
            MMA8(afB, bfB);
            LD_FRAGS(5, st, sBb, afB, bfB);
            MMA8(afA, bfA);
            LD_FRAGS(6, st, sBb, afA, bfA);
            MMA8(afB, bfB);
            LD_FRAGS(7, st, sBb, afB, bfB);
            MMA8(afA, bfA);
            MMA8(afB, bfB);

            if (st == NSTG - 1) {
                // d0,d1 = K(ch), d2,d3 = V(same ch), same columns.
#pragma unroll
                for (int mi = 0; mi < 2; mi++)
#pragma unroll
                    for (int ni = 0; ni < 4; ni++) {
                        float k0 = acc[mi][ni][0], k1 = acc[mi][ni][1];
                        float v0 = acc[mi][ni][2], v1 = acc[mi][ni][3];
                        skv[mi] += k0 * v0 + k1 * v1;
                        skk[mi] += k0 * k0 + k1 * k1;
                        svv[mi] += v0 * v0 + v1 * v1;
                    }
            }
        }
#undef LOAD_B
#undef LD_FRAGS
#undef MMA8

        // quad reduce (lanes 4q..4q+3 share a channel row), per mi group
#pragma unroll
        for (int mi = 0; mi < 2; mi++) {
            skv[mi] += __shfl_down_sync(0xffffffffu, skv[mi], 1);
            skv[mi] += __shfl_down_sync(0xffffffffu, skv[mi], 2);
            skk[mi] += __shfl_down_sync(0xffffffffu, skk[mi], 1);
            skk[mi] += __shfl_down_sync(0xffffffffu, skk[mi], 2);
            svv[mi] += __shfl_down_sync(0xffffffffu, svv[mi], 1);
            svv[mi] += __shfl_down_sync(0xffffffffu, svv[mi], 2);
        }
        __syncthreads();
        if ((lane & 3) == 0) {
#pragma unroll
            for (int mi = 0; mi < 2; mi++) {
                int chl = (wm * 2 + mi) * 8 + (lane >> 2);
                atomicAdd(&sS[chl * 3 + 0], skv[mi]);
                atomicAdd(&sS[chl * 3 + 1], skk[mi]);
                atomicAdd(&sS[chl * 3 + 2], svv[mi]);
            }
        }
        __syncthreads();

        if (tid < 64) {
            float kv  = sS[tid * 3 + 0];
            float kk2 = sS[tid * 3 + 1];
            float vv2 = sS[tid * 3 + 2];
            float cosv = kv / ((sqrtf(kk2) + 1e-12f) * (sqrtf(vv2) + 1e-12f));
            sGate[tid] = 0.5f * cosv + 0.5f;
        }
        __syncthreads();

        // fused output scaling: this tile's 64 channels x 1024 hw
        const float4* X4 = (const float4*)X;
        float4* O4 = (float4*)out;
        const size_t base4 = ((size_t)b * C_ + cb * 64) * (HW_ / 4);
#pragma unroll 4
        for (int i = tid; i < 64 * 256; i += 256) {
            int row = i >> 8;
            float a = sGate[row];
            float4 x = X4[base4 + i];
            float4 o;
            o.x = a * x.x; o.y = a * x.y; o.z = a * x.z; o.w = a * x.w;
            O4[base4 + i] = o;
        }
    }
}

// ---------------------------------------------------------------------------
extern "C" void kernel_launch(void* const* d_in, const int* in_sizes, int n_in,
                              void* d_out, int out_size) {
    const float* X = (const float*)d_in[0];
    const float* W = (const float*)d_in[1];
    float* out = (float*)d_out;

    cudaFuncSetAttribute(norm_wprep_kernel,
                         cudaFuncAttributeMaxDynamicSharedMemorySize, SMEM_N_TOTAL);
    cudaFuncSetAttribute(attn_gemm_kernel,
                         cudaFuncAttributeMaxDynamicSharedMemorySize, SMEM_G_TOTAL);

    norm_wprep_kernel<<<544, 1024, SMEM_N_TOTAL>>>(X, W);
    attn_gemm_kernel<<<152, 256, SMEM_G_TOTAL>>>(X, out);
}